// round 8
// baseline (speedup 1.0000x reference)
#include <cuda_runtime.h>
#include <cuda_fp16.h>
#include <math.h>
#include <stdint.h>

// ---------------- problem constants ----------------
#define BATCH 2
#define CH    256
#define NH    4
#define DK    64          // CH / NH
#define HW_N  2304        // 48*48
#define C2    512         // 2*CH
#define MTILES 18         // HW_N / 128
#define ZPARTS (MTILES*4) // per-(mtile, column-warp) partials

#define ESC 0.18033688011112042f   // 0.125 * log2(e)

// ---------------- scratch (device globals) ----------
__device__ __half g_xs[BATCH*CH*HW_N];
__device__ __half g_ys[BATCH*CH*HW_N];
__device__ __half g_q [BATCH*CH*HW_N];            // [b][n][c]
__device__ __half g_kv[BATCH*C2*HW_N];            // rows 0-255 = k, 256-511 = v
__device__ float  g_x2[BATCH*CH*HW_N];
__device__ float  g_y2[BATCH*CH*HW_N];
__device__ __half g_x2h[BATCH*CH*HW_N];
__device__ __half g_S [(size_t)BATCH*NH*HW_N*HW_N]; // 85 MB: E = exp(S*0.125)
__device__ float  g_Z [BATCH*NH*HW_N];            // invZ
__device__ float  g_Zpart[ZPARTS*BATCH*NH*HW_N];  // per-(mtile,wx) partial row sums
__device__ __half g_wt1h[CH*CH];
__device__ __half g_wt2h[CH*CH];
__device__ __half g_wkv1[C2*CH];
__device__ __half g_wkv2[C2*CH];
__device__ float  g_kvb1[C2];
__device__ float  g_kvb2[C2];
__device__ float  g_pooled[BATCH*C2];
__device__ float  g_gacc[BATCH*2*HW_N];           // gate pre-sigmoid accumulators

__device__ __forceinline__ float sigmoidf_(float v){ return 1.f/(1.f+expf(-v)); }

__device__ __forceinline__ float exp2_fast(float x)
{
    x = fminf(fmaxf(x, -60.f), 60.f);
    float m  = x + 12582912.0f;
    float rn = m - 12582912.0f;
    float r  = x - rn;
    int   iv = __float_as_int(m) - 0x4B400000;
    float p  = 0.0096181291f;
    p = fmaf(p, r, 0.0555041086f);
    p = fmaf(p, r, 0.2402265069f);
    p = fmaf(p, r, 0.6931471806f);
    p = fmaf(p, r, 1.0f);
    return p * __int_as_float((iv + 127) << 23);
}

__device__ __forceinline__ uint32_t smaddr(const void* p){
    return (uint32_t)__cvta_generic_to_shared(p);
}
__device__ __forceinline__ void cpa16(uint32_t dst, const void* src){
    asm volatile("cp.async.cg.shared.global [%0], [%1], 16;" :: "r"(dst), "l"(src));
}
__device__ __forceinline__ void cpa_commit(){
    asm volatile("cp.async.commit_group;" ::: "memory");
}
__device__ __forceinline__ void ldm_x4(uint32_t &r0, uint32_t &r1, uint32_t &r2, uint32_t &r3,
                                       uint32_t a){
    asm volatile("ldmatrix.sync.aligned.m8n8.x4.shared.b16 {%0,%1,%2,%3}, [%4];"
        : "=r"(r0),"=r"(r1),"=r"(r2),"=r"(r3) : "r"(a));
}
__device__ __forceinline__ void ldm_x4t(uint32_t &r0, uint32_t &r1, uint32_t &r2, uint32_t &r3,
                                        uint32_t a){
    asm volatile("ldmatrix.sync.aligned.m8n8.x4.trans.shared.b16 {%0,%1,%2,%3}, [%4];"
        : "=r"(r0),"=r"(r1),"=r"(r2),"=r"(r3) : "r"(a));
}
__device__ __forceinline__ void mma_f16(float (&c)[4], uint32_t a0, uint32_t a1,
                                        uint32_t a2, uint32_t a3,
                                        uint32_t b0, uint32_t b1)
{
    asm volatile("mma.sync.aligned.m16n8k16.row.col.f32.f16.f16.f32 "
        "{%0,%1,%2,%3}, {%4,%5,%6,%7}, {%8,%9}, {%0,%1,%2,%3};"
        : "+f"(c[0]), "+f"(c[1]), "+f"(c[2]), "+f"(c[3])
        : "r"(a0), "r"(a1), "r"(a2), "r"(a3), "r"(b0), "r"(b1));
}

// ---------------- prep: 2x weight transpose + kv weight pack + gacc zero ----
__global__ void prep_kernel(const float* __restrict__ qw1, const float* __restrict__ qw2,
                            const float* __restrict__ kw1, const float* __restrict__ vw1,
                            const float* __restrict__ kb1, const float* __restrict__ vb1,
                            const float* __restrict__ kw2, const float* __restrict__ vw2,
                            const float* __restrict__ kb2, const float* __restrict__ vb2)
{
    int bid = blockIdx.x, t = threadIdx.x;
    if (bid < 128){                                  // q-weight transposes
        int which = bid >> 6, tile = bid & 63;
        const float* in  = which ? qw2 : qw1;
        __half*      out = which ? g_wt2h : g_wt1h;
        __shared__ float tl[32][33];
        int bx = (tile & 7)*32, by = (tile >> 3)*32;
        int tx = t & 31, ty = t >> 5;                // 32x8
        #pragma unroll
        for (int i = 0; i < 32; i += 8)
            tl[ty+i][tx] = in[(by+ty+i)*CH + bx+tx];
        __syncthreads();
        #pragma unroll
        for (int i = 0; i < 32; i += 8)
            out[(bx+ty+i)*CH + by+tx] = __float2half_rn(tl[tx][ty+i]);
    } else if (bid < 128 + 1024){                    // kv weight pack
        int idx = (bid-128)*256 + t;                 // over 2*C2*CH
        int which = idx / (C2*CH);
        int li = idx % (C2*CH);
        int row = li / CH, col = li % CH;
        const float* kw = which ? kw2 : kw1;
        const float* vw = which ? vw2 : vw1;
        __half* dst = which ? g_wkv2 : g_wkv1;
        dst[li] = __float2half_rn(row < CH ? kw[row*CH + col] : vw[(row-CH)*CH + col]);
        if (li < C2){
            const float* kb = which ? kb2 : kb1;
            const float* vb = which ? vb2 : vb1;
            float* db = which ? g_kvb2 : g_kvb1;
            db[li] = (li < CH) ? kb[li] : vb[li-CH];
        }
    } else {                                         // zero gate accumulators
        for (int j = t; j < BATCH*2*HW_N; j += 256) g_gacc[j] = 0.f;
    }
}

// ---------------- channel-mean pooling ----------------
__global__ void pool_kernel(const float* __restrict__ x, const float* __restrict__ y)
{
    int idx = blockIdx.x;
    int b = idx / C2, ch = idx % C2;
    const float* src = (ch < CH) ? (x + ((long)b*CH + ch)*HW_N)
                                 : (y + ((long)b*CH + (ch-CH))*HW_N);
    float s = 0.f;
    for (int i = threadIdx.x; i < HW_N; i += 256) s += src[i];
    __shared__ float red[256];
    red[threadIdx.x] = s; __syncthreads();
    for (int st = 128; st > 0; st >>= 1) {
        if (threadIdx.x < st) red[threadIdx.x] += red[threadIdx.x+st];
        __syncthreads();
    }
    if (threadIdx.x == 0) g_pooled[idx] = red[0] / (float)HW_N;
}

// ---------------- fused SE-MLP + elementwise scale ----------------
__global__ void sescale_kernel(const float* __restrict__ x, const float* __restrict__ y,
                               const float* __restrict__ w1, const float* __restrict__ b1,
                               const float* __restrict__ w2, const float* __restrict__ b2)
{
    int bid = blockIdx.x, t = threadIdx.x;
    int m0 = (bid % 9)*256;
    int c  = (bid / 9) % CH;
    int b  = bid / (9*CH);

    __shared__ float sp[C2];
    __shared__ float sh[DK];
    __shared__ float red[256];
    __shared__ float sxy[2];

    sp[t]       = g_pooled[b*C2 + t];
    sp[t + 256] = g_pooled[b*C2 + t + 256];
    __syncthreads();

    {
        int h = t & 63, part = t >> 6;
        float s = 0.f;
        const float* wr = w1 + h*C2 + part*128;
        const float* pr = sp + part*128;
        #pragma unroll 8
        for (int j = 0; j < 128; j++) s = fmaf(wr[j], pr[j], s);
        red[part*64 + h] = s;
    }
    __syncthreads();
    if (t < DK)
        sh[t] = fmaxf(red[t] + red[64+t] + red[128+t] + red[192+t] + b1[t], 0.f);
    __syncthreads();

    if (t < 64)            red[t] = w2[c*DK + t]           * sh[t];
    else if (t < 128)      red[t] = w2[(CH+c)*DK + (t-64)] * sh[t-64];
    __syncthreads();
    for (int st = 32; st > 0; st >>= 1){
        if (t < st) red[t] += red[t+st];
        else if (t >= 64 && t < 64+st) red[t] += red[t+st];
        __syncthreads();
    }
    if (t == 0) sxy[0] = 1.f + sigmoidf_(red[0]  + b2[c]);
    if (t == 1) sxy[1] = 1.f + sigmoidf_(red[64] + b2[CH+c]);
    __syncthreads();

    long base = ((long)b*CH + c)*HW_N + m0;
    g_xs[base + t] = __float2half_rn(x[base + t] * sxy[0]);
    g_ys[base + t] = __float2half_rn(y[base + t] * sxy[1]);
}

__global__ void zfill_kernel(float* __restrict__ p, int n)
{
    int i = blockIdx.x*blockDim.x + threadIdx.x;
    if (i < n) p[i] = 0.f;
}

// invZ from ZPARTS partials
__global__ void zinv_kernel()
{
    int i = blockIdx.x*blockDim.x + threadIdx.x;
    if (i >= BATCH*NH*HW_N) return;
    float s = 0.f;
    #pragma unroll
    for (int p = 0; p < ZPARTS; p++) s += g_Zpart[(long)p*(BATCH*NH*HW_N) + i];
    g_Z[i] = 1.0f / s;
}

// scale v rows (g_kv rows 256..511) by invZ[(b,h,n)]
__global__ void vscale_kernel()
{
    long i = (long)blockIdx.x*blockDim.x + threadIdx.x;
    if (i >= (long)BATCH*CH*HW_N) return;
    int b = (int)(i / (CH*HW_N));
    int c = (int)((i / HW_N) % CH);
    int n = (int)(i % HW_N);
    long off = ((long)b*C2 + CH + c)*HW_N + n;
    float z = g_Z[((long)b*NH + (c >> 6))*HW_N + n];
    g_kv[off] = __float2half_rn(__half2float(g_kv[off]) * z);
}

__global__ void f2h_kernel(const float* __restrict__ src, __half* __restrict__ dst, int n)
{
    int i = blockIdx.x*blockDim.x + threadIdx.x;
    if (i < n) dst[i] = __float2half_rn(src[i]);
}

// ================= all-half cp.async tensor-core GEMM =================
template<int BK, int ST, int BM, int BN, int WM, int WN,
         bool TRA, int BIAS, bool EXPZ, bool CHALF, int SPLITK>
__global__ void __launch_bounds__(256)
hgemm(const __half* __restrict__ A, const __half* __restrict__ B,
      void* __restrict__ Cv, const float* __restrict__ bias,
      float* __restrict__ Zp,
      int K, int lda, int ldb, int ldc, int zdiv,
      long long sA1, long long sA2, long long sB1, long long sB2,
      long long sC1, long long sC2)
{
    constexpr int WCOLS = BN / WN;
    constexpr int MF = WM / 16;
    constexpr int NF = WN / 8;
    constexpr int PAD = 8;
    constexpr int A_CH = (BM*BK/8)/256;
    constexpr int B_CH = (BK*BN/8)/256;

    __shared__ __half As[ST][TRA ? BK : BM][(TRA ? BM : BK) + PAD];
    __shared__ __half Bs[ST][BK][BN + PAD];

    int z  = blockIdx.z;
    int z1 = z / zdiv, z2 = z - z1*zdiv;
    A += z1*sA1 + z2*sA2;
    B += z1*sB1 + z2*sB2;
    float*  Cf = (EXPZ || CHALF) ? nullptr : ((float*)Cv + z1*sC1 + z2*sC2);
    __half* Ch = (EXPZ || CHALF) ? ((__half*)Cv + z1*sC1 + z2*sC2) : nullptr;

    int bm, kbase, Keff;
    if (SPLITK > 1){ bm = 0; kbase = blockIdx.y*(K/SPLITK); Keff = K/SPLITK; }
    else           { bm = blockIdx.y*BM; kbase = 0; Keff = K; }
    int bn = blockIdx.x*BN;

    int t    = threadIdx.x;
    int warp = t >> 5, lane = t & 31;
    int g = lane >> 2, t4 = lane & 3;
    int wy = warp / WCOLS, wx = warp % WCOLS;

    auto issue = [&](int s, int k0){
        #pragma unroll
        for (int i = 0; i < A_CH; i++){
            int idx = t + 256*i;
            if (TRA){
                int k = idx/(BM/8), m8 = idx%(BM/8);
                cpa16(smaddr(&As[s][k][m8*8]), &A[(long)(k0+k)*lda + bm + m8*8]);
            } else {
                int m = idx/(BK/8), k8 = idx%(BK/8);
                cpa16(smaddr(&As[s][m][k8*8]), &A[(long)(bm+m)*lda + k0 + k8*8]);
            }
        }
        #pragma unroll
        for (int i = 0; i < B_CH; i++){
            int idx = t + 256*i;
            int k = idx/(BN/8), n8 = idx%(BN/8);
            cpa16(smaddr(&Bs[s][k][n8*8]), &B[(long)(k0+k)*ldb + bn + n8*8]);
        }
        cpa_commit();
    };

    float acc[MF][NF][4] = {};

    int nT = Keff / BK;
    issue(0, kbase);
    if (ST > 1 && nT > 1) issue(1, kbase + BK);

    for (int tI = 0; tI < nT; tI++){
        if (ST > 1 && tI < nT-1) asm volatile("cp.async.wait_group 1;" ::: "memory");
        else                     asm volatile("cp.async.wait_group 0;" ::: "memory");
        __syncthreads();
        if (ST > 1 && tI + 2 < nT) issue((tI+2)%ST, kbase + (tI+2)*BK);

        int cur = tI % ST;
        #pragma unroll
        for (int kc = 0; kc < BK/16; kc++){
            uint32_t af[MF][4]; uint32_t bf[NF][2];
            #pragma unroll
            for (int mf = 0; mf < MF; mf++){
                if (TRA){
                    uint32_t r0,r1,r2,r3;
                    uint32_t a = smaddr(&As[cur][kc*16 + (lane & 15)]
                                                [wy*WM + mf*16 + ((lane >> 4) << 3)]);
                    ldm_x4t(r0, r1, r2, r3, a);
                    af[mf][0]=r0; af[mf][1]=r2; af[mf][2]=r1; af[mf][3]=r3;
                } else {
                    uint32_t a = smaddr(&As[cur][wy*WM + mf*16 + (lane & 15)]
                                                [kc*16 + ((lane >> 4) << 3)]);
                    ldm_x4(af[mf][0], af[mf][1], af[mf][2], af[mf][3], a);
                }
            }
            #pragma unroll
            for (int nf2 = 0; nf2 < NF/2; nf2++){
                uint32_t a = smaddr(&Bs[cur][kc*16 + (lane & 15)]
                                            [wx*WN + nf2*16 + ((lane >> 4) << 3)]);
                ldm_x4t(bf[nf2*2][0], bf[nf2*2][1], bf[nf2*2+1][0], bf[nf2*2+1][1], a);
            }
            #pragma unroll
            for (int mf = 0; mf < MF; mf++)
                #pragma unroll
                for (int nf = 0; nf < NF; nf++)
                    mma_f16(acc[mf][nf], af[mf][0], af[mf][1], af[mf][2], af[mf][3],
                            bf[nf][0], bf[nf][1]);
        }
    }

    // ---------------- epilogue ----------------
    #pragma unroll
    for (int mf = 0; mf < MF; mf++){
        int rbase = bm + wy*WM + mf*16 + g;
        #pragma unroll
        for (int half = 0; half < 2; half++){
            int r = rbase + half*8;
            float bM = (BIAS == 1) ? bias[r] : 0.f;
            float rowsum = 0.f;
            #pragma unroll
            for (int nf = 0; nf < NF; nf++){
                int cI = bn + wx*WN + nf*8 + t4*2;
                float v0 = acc[mf][nf][half*2 + 0];
                float v1 = acc[mf][nf][half*2 + 1];
                if (EXPZ){
                    v0 = exp2_fast(v0*ESC);
                    v1 = exp2_fast(v1*ESC);
                    rowsum += v0 + v1;
                    *reinterpret_cast<__half2*>(&Ch[(long)r*ldc + cI]) =
                        __floats2half2_rn(v0, v1);
                } else {
                    if (BIAS == 1){ v0 += bM; v1 += bM; }
                    if (BIAS == 2){ v0 += bias[cI]; v1 += bias[cI+1]; }
                    if (CHALF){
                        *reinterpret_cast<__half2*>(&Ch[(long)r*ldc + cI]) =
                            __floats2half2_rn(v0, v1);
                    } else if (SPLITK > 1){
                        atomicAdd(&Cf[(long)r*ldc + cI],     v0);
                        atomicAdd(&Cf[(long)r*ldc + cI + 1], v1);
                    } else {
                        *reinterpret_cast<float2*>(&Cf[(long)r*ldc + cI]) = make_float2(v0, v1);
                    }
                }
            }
            if (EXPZ){
                rowsum += __shfl_xor_sync(0xffffffffu, rowsum, 1);
                rowsum += __shfl_xor_sync(0xffffffffu, rowsum, 2);
                // per-(mtile, column-warp) slot: race-free plain store
                if (t4 == 0)
                    Zp[((long)(blockIdx.x*WCOLS + wx)*(BATCH*NH) + z)*HW_N + r] = rowsum;
            }
        }
    }
}

// ---------------- gating: channel-split partial dot products ----------------
__global__ void gate_part(const float* __restrict__ gw)
{
    int i = blockIdx.x*256 + threadIdx.x;    // over BATCH*HW_N
    int b = i / HW_N, m = i % HW_N;
    int c0 = blockIdx.y*32;
    const float* xb = g_x2 + (long)b*CH*HW_N + m;
    const float* yb = g_y2 + (long)b*CH*HW_N + m;
    float s0 = 0.f, s1 = 0.f;
    #pragma unroll 8
    for (int c = c0; c < c0+32; c++){
        float xv = xb[(long)c*HW_N];
        s0 = fmaf(gw[c],      xv, s0);
        s1 = fmaf(gw[C2 + c], xv, s1);
    }
    #pragma unroll 8
    for (int c = c0; c < c0+32; c++){
        float yv = yb[(long)c*HW_N];
        s0 = fmaf(gw[CH + c],      yv, s0);
        s1 = fmaf(gw[C2 + CH + c], yv, s1);
    }
    atomicAdd(&g_gacc[b*2*HW_N + m],        s0);
    atomicAdd(&g_gacc[b*2*HW_N + HW_N + m], s1);
}

// ---------------- final gated writeback (sigmoid inline) ----------------
__global__ void final_kernel(float* __restrict__ out, const float* __restrict__ gb)
{
    long i = (long)blockIdx.x*blockDim.x + threadIdx.x;
    if (i >= (long)BATCH*CH*HW_N) return;
    int b = (int)(i / (CH*HW_N));
    int m = (int)(i % HW_N);
    float g0 = 1.f + sigmoidf_(g_gacc[b*2*HW_N + m]        + gb[0]);
    float g1 = 1.f + sigmoidf_(g_gacc[b*2*HW_N + HW_N + m] + gb[1]);
    out[i]                       = g_x2[i] * g0;
    out[(long)BATCH*CH*HW_N + i] = g_y2[i] * g1;
}

// ---------------- host orchestration ----------------
extern "C" void kernel_launch(void* const* d_in, const int* in_sizes, int n_in,
                              void* d_out, int out_size)
{
    const float* x      = (const float*)d_in[0];
    const float* y      = (const float*)d_in[1];
    const float* fc1w   = (const float*)d_in[2];
    const float* fc1b   = (const float*)d_in[3];
    const float* fc2w   = (const float*)d_in[4];
    const float* fc2b   = (const float*)d_in[5];
    const float* t1_qw  = (const float*)d_in[6];
    const float* t1_qb  = (const float*)d_in[7];
    const float* t1_kw  = (const float*)d_in[8];
    const float* t1_kb  = (const float*)d_in[9];
    const float* t1_vw  = (const float*)d_in[10];
    const float* t1_vb  = (const float*)d_in[11];
    const float* t2_qw  = (const float*)d_in[12];
    const float* t2_qb  = (const float*)d_in[13];
    const float* t2_kw  = (const float*)d_in[14];
    const float* t2_kb  = (const float*)d_in[15];
    const float* t2_vw  = (const float*)d_in[16];
    const float* t2_vb  = (const float*)d_in[17];
    const float* gate_w = (const float*)d_in[18];
    const float* gate_b = (const float*)d_in[19];

    float *x2, *y2, *Zpart, *kvb1, *kvb2;
    __half *xs, *ys, *q, *kv, *S, *x2h, *wt1h, *wt2h, *wkv1, *wkv2;
    cudaGetSymbolAddress((void**)&xs,    g_xs);
    cudaGetSymbolAddress((void**)&ys,    g_ys);
    cudaGetSymbolAddress((void**)&q,     g_q);
    cudaGetSymbolAddress((void**)&kv,    g_kv);
    cudaGetSymbolAddress((void**)&S,     g_S);
    cudaGetSymbolAddress((void**)&x2,    g_x2);
    cudaGetSymbolAddress((void**)&y2,    g_y2);
    cudaGetSymbolAddress((void**)&x2h,   g_x2h);
    cudaGetSymbolAddress((void**)&Zpart, g_Zpart);
    cudaGetSymbolAddress((void**)&wt1h,  g_wt1h);
    cudaGetSymbolAddress((void**)&wt2h,  g_wt2h);
    cudaGetSymbolAddress((void**)&wkv1,  g_wkv1);
    cudaGetSymbolAddress((void**)&wkv2,  g_wkv2);
    cudaGetSymbolAddress((void**)&kvb1,  g_kvb1);
    cudaGetSymbolAddress((void**)&kvb2,  g_kvb2);

    const long total = (long)BATCH*CH*HW_N;
    const long long NN  = (long long)HW_N*HW_N;
    const long long CN  = (long long)CH*HW_N;
    const long long HN  = (long long)DK*HW_N;

    // --- prologue (slot 4 = first q-conv GEMM for ncu) ---
    prep_kernel<<<1153, 256>>>(t1_qw, t2_qw, t1_kw, t1_vw, t1_kb, t1_vb,
                               t2_kw, t2_vw, t2_kb, t2_vb);             // 1
    pool_kernel<<<BATCH*C2, 256>>>(x, y);                               // 2
    sescale_kernel<<<BATCH*CH*9, 256>>>(x, y, fc1w, fc1b, fc2w, fc2b);  // 3

    auto rtrans = [&](const __half* qin, const __half* kvin,
                      const __half* wtq, const float* qb,
                      const __half* wkv, const float* kvb, float* outp)
    {
        // q_t[b][n][c] = sum_c' qin[b][c'][n] * wtq[c'][c] + qb[c]
        hgemm<32,3, 128,64,32,32, true,2,false,true,1>
            <<<dim3(CH/64, HW_N/128, BATCH), 256>>>(
            qin, wtq, q, qb, nullptr,
            CH, HW_N, CH, CH,
            1, CN, 0, 0, 0, CN, 0);
        // kv[b][o][n] = sum_c wkv[o][c]*kvin[b][c][n] + kvb[o]
        hgemm<32,3, 128,128,64,32, false,1,false,true,1>
            <<<dim3(HW_N/128, C2/128, BATCH), 256>>>(
            wkv, kvin, kv, kvb, nullptr,
            CH, CH, HW_N, HW_N,
            1, 0, 0, CN, 0, (long long)C2*HW_N, 0);
        // E[z][n][m] = half(exp2(S*ESC)); Zpart[(mtile,wx)][z][n] = warp row sums
        hgemm<64,1, 128,128,64,32, false,0,true,false,1>
            <<<dim3(HW_N/128, HW_N/128, BATCH*NH), 256>>>(
            q, kv, S, nullptr, Zpart,
            DK, CH, HW_N, HW_N,
            NH, (long long)HW_N*CH, DK, (long long)C2*HW_N, HN,
            (long long)NH*NN, NN);
        zinv_kernel<<<(BATCH*NH*HW_N + 255)/256, 256>>>();
        vscale_kernel<<<(int)((total + 255)/256), 256>>>();
        zfill_kernel<<<(int)((total + 255)/256), 256>>>(outp, (int)total);
        // out[b][h*64+d][m] = sum_n vZ[d][n] * E[z][n][m]   (split-K=3)
        hgemm<32,3, 64,128,32,32, false,0,false,false,3>
            <<<dim3(HW_N/128, 3, BATCH*NH), 256>>>(
            kv + (long)CH*HW_N, S, outp, nullptr, nullptr,
            HW_N, HW_N, HW_N, HW_N,
            NH, (long long)C2*HW_N, HN, (long long)NH*NN, NN, CN, HN);
    };

    // RTrans 1: x = attn(q=xs, k=ys, v=ys)
    rtrans(xs, ys, wt1h, t1_qb, wkv1, kvb1, x2);
    f2h_kernel<<<(int)((total + 255)/256), 256>>>(x2, x2h, (int)total);
    // RTrans 2: y = attn(q=ys, k=x2, v=x2)
    rtrans(ys, x2h, wt2h, t2_qb, wkv2, kvb2, y2);

    // --- RGating + final writeback ---
    gate_part<<<dim3((BATCH*HW_N)/256, CH/32), 256>>>(gate_w);
    final_kernel<<<(int)((total + 255)/256), 256>>>((float*)d_out, gate_b);
}

// round 9
// speedup vs baseline: 2.5882x; 2.5882x over previous
#include <cuda_runtime.h>
#include <cuda_fp16.h>
#include <math.h>
#include <stdint.h>

// ---------------- problem constants ----------------
#define BATCH 2
#define CH    256
#define NH    4
#define DK    64          // CH / NH
#define HW_N  2304        // 48*48
#define C2    512         // 2*CH
#define MTILES 18         // HW_N / 128
#define ZPARTS (MTILES*4) // per-(mtile, column-warp) partials

#define ESC 0.18033688011112042f   // 0.125 * log2(e)

// ---------------- scratch (device globals) ----------
__device__ __half g_xs[BATCH*CH*HW_N];
__device__ __half g_ys[BATCH*CH*HW_N];
__device__ __half g_q [BATCH*CH*HW_N];            // [b][n][c]
__device__ __half g_kv[BATCH*C2*HW_N];            // rows 0-255 = k, 256-511 = v
__device__ float  g_x2[BATCH*CH*HW_N];
__device__ float  g_y2[BATCH*CH*HW_N];
__device__ __half g_x2h[BATCH*CH*HW_N];
__device__ __half g_S [(size_t)BATCH*NH*HW_N*HW_N]; // 85 MB: E = exp(S*0.125)
__device__ float  g_Z [BATCH*NH*HW_N];            // invZ
__device__ float  g_Zpart[ZPARTS*BATCH*NH*HW_N];  // per-(mtile,wx) partial row sums
__device__ __half g_wt1h[CH*CH];
__device__ __half g_wt2h[CH*CH];
__device__ __half g_wkv1[C2*CH];
__device__ __half g_wkv2[C2*CH];
__device__ float  g_kvb1[C2];
__device__ float  g_kvb2[C2];
__device__ float  g_pooled[BATCH*C2];
__device__ float  g_sescale[BATCH*C2];            // 1 + sigmoid(f)
__device__ float  g_gacc[BATCH*2*HW_N];           // gate pre-sigmoid accumulators

__device__ __forceinline__ float sigmoidf_(float v){ return 1.f/(1.f+expf(-v)); }

__device__ __forceinline__ float exp2_fast(float x)
{
    x = fminf(fmaxf(x, -60.f), 60.f);
    float m  = x + 12582912.0f;
    float rn = m - 12582912.0f;
    float r  = x - rn;
    int   iv = __float_as_int(m) - 0x4B400000;
    float p  = 0.0096181291f;
    p = fmaf(p, r, 0.0555041086f);
    p = fmaf(p, r, 0.2402265069f);
    p = fmaf(p, r, 0.6931471806f);
    p = fmaf(p, r, 1.0f);
    return p * __int_as_float((iv + 127) << 23);
}

__device__ __forceinline__ uint32_t smaddr(const void* p){
    return (uint32_t)__cvta_generic_to_shared(p);
}
__device__ __forceinline__ void cpa16(uint32_t dst, const void* src){
    asm volatile("cp.async.cg.shared.global [%0], [%1], 16;" :: "r"(dst), "l"(src));
}
__device__ __forceinline__ void cpa_commit(){
    asm volatile("cp.async.commit_group;" ::: "memory");
}
__device__ __forceinline__ void ldm_x4(uint32_t &r0, uint32_t &r1, uint32_t &r2, uint32_t &r3,
                                       uint32_t a){
    asm volatile("ldmatrix.sync.aligned.m8n8.x4.shared.b16 {%0,%1,%2,%3}, [%4];"
        : "=r"(r0),"=r"(r1),"=r"(r2),"=r"(r3) : "r"(a));
}
__device__ __forceinline__ void ldm_x4t(uint32_t &r0, uint32_t &r1, uint32_t &r2, uint32_t &r3,
                                        uint32_t a){
    asm volatile("ldmatrix.sync.aligned.m8n8.x4.trans.shared.b16 {%0,%1,%2,%3}, [%4];"
        : "=r"(r0),"=r"(r1),"=r"(r2),"=r"(r3) : "r"(a));
}
__device__ __forceinline__ void mma_f16(float (&c)[4], uint32_t a0, uint32_t a1,
                                        uint32_t a2, uint32_t a3,
                                        uint32_t b0, uint32_t b1)
{
    asm volatile("mma.sync.aligned.m16n8k16.row.col.f32.f16.f16.f32 "
        "{%0,%1,%2,%3}, {%4,%5,%6,%7}, {%8,%9}, {%0,%1,%2,%3};"
        : "+f"(c[0]), "+f"(c[1]), "+f"(c[2]), "+f"(c[3])
        : "r"(a0), "r"(a1), "r"(a2), "r"(a3), "r"(b0), "r"(b1));
}

// ---- prep: weight transposes + kv pack + gacc zero + channel pooling ----
__global__ void prep_kernel(const float* __restrict__ x, const float* __restrict__ y,
                            const float* __restrict__ qw1, const float* __restrict__ qw2,
                            const float* __restrict__ kw1, const float* __restrict__ vw1,
                            const float* __restrict__ kb1, const float* __restrict__ vb1,
                            const float* __restrict__ kw2, const float* __restrict__ vw2,
                            const float* __restrict__ kb2, const float* __restrict__ vb2)
{
    int bid = blockIdx.x, t = threadIdx.x;
    if (bid < 128){                                  // q-weight transposes
        int which = bid >> 6, tile = bid & 63;
        const float* in  = which ? qw2 : qw1;
        __half*      out = which ? g_wt2h : g_wt1h;
        __shared__ float tl[32][33];
        int bx = (tile & 7)*32, by = (tile >> 3)*32;
        int tx = t & 31, ty = t >> 5;                // 32x8
        #pragma unroll
        for (int i = 0; i < 32; i += 8)
            tl[ty+i][tx] = in[(by+ty+i)*CH + bx+tx];
        __syncthreads();
        #pragma unroll
        for (int i = 0; i < 32; i += 8)
            out[(bx+ty+i)*CH + by+tx] = __float2half_rn(tl[tx][ty+i]);
    } else if (bid < 128 + 1024){                    // kv weight pack
        int idx = (bid-128)*256 + t;                 // over 2*C2*CH
        int which = idx / (C2*CH);
        int li = idx % (C2*CH);
        int row = li / CH, col = li % CH;
        const float* kw = which ? kw2 : kw1;
        const float* vw = which ? vw2 : vw1;
        __half* dst = which ? g_wkv2 : g_wkv1;
        dst[li] = __float2half_rn(row < CH ? kw[row*CH + col] : vw[(row-CH)*CH + col]);
        if (li < C2){
            const float* kb = which ? kb2 : kb1;
            const float* vb = which ? vb2 : vb1;
            float* db = which ? g_kvb2 : g_kvb1;
            db[li] = (li < CH) ? kb[li] : vb[li-CH];
        }
    } else if (bid == 128 + 1024){                   // zero gate accumulators
        for (int j = t; j < BATCH*2*HW_N; j += 256) g_gacc[j] = 0.f;
    } else {                                         // channel-mean pooling
        int idx = bid - (128 + 1024 + 1);            // over BATCH*C2
        int b = idx / C2, ch = idx % C2;
        const float* src = (ch < CH) ? (x + ((long)b*CH + ch)*HW_N)
                                     : (y + ((long)b*CH + (ch-CH))*HW_N);
        float s = 0.f;
        for (int i = t; i < HW_N; i += 256) s += src[i];
        __shared__ float red[256];
        red[t] = s; __syncthreads();
        for (int st = 128; st > 0; st >>= 1){
            if (t < st) red[t] += red[t+st];
            __syncthreads();
        }
        if (t == 0) g_pooled[idx] = red[0] / (float)HW_N;
    }
}

// ---------------- SE MLP (tiny, 2 blocks) ----------------
__global__ void se_kernel(const float* __restrict__ w1, const float* __restrict__ b1,
                          const float* __restrict__ w2, const float* __restrict__ b2)
{
    int b = blockIdx.x, t = threadIdx.x;   // 512 threads
    __shared__ float sp[C2], sh[DK];
    sp[t] = g_pooled[b*C2 + t];
    __syncthreads();
    if (t < DK) {
        float s = b1[t];
        for (int c = 0; c < C2; c++) s += w1[t*C2 + c] * sp[c];
        sh[t] = fmaxf(s, 0.f);
    }
    __syncthreads();
    float f = b2[t];
    for (int j = 0; j < DK; j++) f += w2[t*DK + j] * sh[j];
    g_sescale[b*C2 + t] = 1.f + sigmoidf_(f);
}

// ---------------- elementwise SE scale (coalesced) ----------------
__global__ void scale_kernel(const float* __restrict__ x, const float* __restrict__ y)
{
    long i = (long)blockIdx.x*blockDim.x + threadIdx.x;
    if (i >= (long)BATCH*CH*HW_N) return;
    int b = (int)(i / (CH*HW_N));
    int c = (int)((i / HW_N) % CH);
    g_xs[i] = __float2half_rn(x[i] * g_sescale[b*C2 + c]);
    g_ys[i] = __float2half_rn(y[i] * g_sescale[b*C2 + CH + c]);
}

__global__ void zfill_kernel(float* __restrict__ p, int n)
{
    int i = blockIdx.x*blockDim.x + threadIdx.x;
    if (i < n) p[i] = 0.f;
}

// invZ from ZPARTS partials
__global__ void zinv_kernel()
{
    int i = blockIdx.x*blockDim.x + threadIdx.x;
    if (i >= BATCH*NH*HW_N) return;
    float s = 0.f;
    #pragma unroll
    for (int p = 0; p < ZPARTS; p++) s += g_Zpart[(long)p*(BATCH*NH*HW_N) + i];
    g_Z[i] = 1.0f / s;
}

// scale v rows (g_kv rows 256..511) by invZ[(b,h,n)]
__global__ void vscale_kernel()
{
    long i = (long)blockIdx.x*blockDim.x + threadIdx.x;
    if (i >= (long)BATCH*CH*HW_N) return;
    int b = (int)(i / (CH*HW_N));
    int c = (int)((i / HW_N) % CH);
    int n = (int)(i % HW_N);
    long off = ((long)b*C2 + CH + c)*HW_N + n;
    float z = g_Z[((long)b*NH + (c >> 6))*HW_N + n];
    g_kv[off] = __float2half_rn(__half2float(g_kv[off]) * z);
}

__global__ void f2h_kernel(const float* __restrict__ src, __half* __restrict__ dst, int n)
{
    int i = blockIdx.x*blockDim.x + threadIdx.x;
    if (i < n) dst[i] = __float2half_rn(src[i]);
}

// ================= all-half cp.async tensor-core GEMM =================
template<int BK, int ST, int BM, int BN, int WM, int WN,
         bool TRA, int BIAS, bool EXPZ, bool CHALF, int SPLITK>
__global__ void __launch_bounds__(256)
hgemm(const __half* __restrict__ A, const __half* __restrict__ B,
      void* __restrict__ Cv, const float* __restrict__ bias,
      float* __restrict__ Zp,
      int K, int lda, int ldb, int ldc, int zdiv,
      long long sA1, long long sA2, long long sB1, long long sB2,
      long long sC1, long long sC2)
{
    constexpr int WCOLS = BN / WN;
    constexpr int MF = WM / 16;
    constexpr int NF = WN / 8;
    constexpr int PAD = 8;
    constexpr int A_CH = (BM*BK/8)/256;
    constexpr int B_CH = (BK*BN/8)/256;

    __shared__ __half As[ST][TRA ? BK : BM][(TRA ? BM : BK) + PAD];
    __shared__ __half Bs[ST][BK][BN + PAD];

    int z  = blockIdx.z;
    int z1 = z / zdiv, z2 = z - z1*zdiv;
    A += z1*sA1 + z2*sA2;
    B += z1*sB1 + z2*sB2;
    float*  Cf = (EXPZ || CHALF) ? nullptr : ((float*)Cv + z1*sC1 + z2*sC2);
    __half* Ch = (EXPZ || CHALF) ? ((__half*)Cv + z1*sC1 + z2*sC2) : nullptr;

    int bm, kbase, Keff;
    if (SPLITK > 1){ bm = 0; kbase = blockIdx.y*(K/SPLITK); Keff = K/SPLITK; }
    else           { bm = blockIdx.y*BM; kbase = 0; Keff = K; }
    int bn = blockIdx.x*BN;

    int t    = threadIdx.x;
    int warp = t >> 5, lane = t & 31;
    int g = lane >> 2, t4 = lane & 3;
    int wy = warp / WCOLS, wx = warp % WCOLS;

    auto issue = [&](int s, int k0){
        #pragma unroll
        for (int i = 0; i < A_CH; i++){
            int idx = t + 256*i;
            if (TRA){
                int k = idx/(BM/8), m8 = idx%(BM/8);
                cpa16(smaddr(&As[s][k][m8*8]), &A[(long)(k0+k)*lda + bm + m8*8]);
            } else {
                int m = idx/(BK/8), k8 = idx%(BK/8);
                cpa16(smaddr(&As[s][m][k8*8]), &A[(long)(bm+m)*lda + k0 + k8*8]);
            }
        }
        #pragma unroll
        for (int i = 0; i < B_CH; i++){
            int idx = t + 256*i;
            int k = idx/(BN/8), n8 = idx%(BN/8);
            cpa16(smaddr(&Bs[s][k][n8*8]), &B[(long)(k0+k)*ldb + bn + n8*8]);
        }
        cpa_commit();
    };

    float acc[MF][NF][4] = {};

    int nT = Keff / BK;
    issue(0, kbase);
    if (ST > 1 && nT > 1) issue(1, kbase + BK);

    for (int tI = 0; tI < nT; tI++){
        if (ST > 1 && tI < nT-1) asm volatile("cp.async.wait_group 1;" ::: "memory");
        else                     asm volatile("cp.async.wait_group 0;" ::: "memory");
        __syncthreads();
        if (ST > 1 && tI + 2 < nT) issue((tI+2)%ST, kbase + (tI+2)*BK);

        int cur = tI % ST;
        #pragma unroll
        for (int kc = 0; kc < BK/16; kc++){
            uint32_t af[MF][4]; uint32_t bf[NF][2];
            #pragma unroll
            for (int mf = 0; mf < MF; mf++){
                if (TRA){
                    uint32_t r0,r1,r2,r3;
                    uint32_t a = smaddr(&As[cur][kc*16 + (lane & 15)]
                                                [wy*WM + mf*16 + ((lane >> 4) << 3)]);
                    ldm_x4t(r0, r1, r2, r3, a);
                    af[mf][0]=r0; af[mf][1]=r2; af[mf][2]=r1; af[mf][3]=r3;
                } else {
                    uint32_t a = smaddr(&As[cur][wy*WM + mf*16 + (lane & 15)]
                                                [kc*16 + ((lane >> 4) << 3)]);
                    ldm_x4(af[mf][0], af[mf][1], af[mf][2], af[mf][3], a);
                }
            }
            #pragma unroll
            for (int nf2 = 0; nf2 < NF/2; nf2++){
                uint32_t a = smaddr(&Bs[cur][kc*16 + (lane & 15)]
                                            [wx*WN + nf2*16 + ((lane >> 4) << 3)]);
                ldm_x4t(bf[nf2*2][0], bf[nf2*2][1], bf[nf2*2+1][0], bf[nf2*2+1][1], a);
            }
            #pragma unroll
            for (int mf = 0; mf < MF; mf++)
                #pragma unroll
                for (int nf = 0; nf < NF; nf++)
                    mma_f16(acc[mf][nf], af[mf][0], af[mf][1], af[mf][2], af[mf][3],
                            bf[nf][0], bf[nf][1]);
        }
    }

    // ---------------- epilogue ----------------
    #pragma unroll
    for (int mf = 0; mf < MF; mf++){
        int rbase = bm + wy*WM + mf*16 + g;
        #pragma unroll
        for (int half = 0; half < 2; half++){
            int r = rbase + half*8;
            float bM = (BIAS == 1) ? bias[r] : 0.f;
            float rowsum = 0.f;
            #pragma unroll
            for (int nf = 0; nf < NF; nf++){
                int cI = bn + wx*WN + nf*8 + t4*2;
                float v0 = acc[mf][nf][half*2 + 0];
                float v1 = acc[mf][nf][half*2 + 1];
                if (EXPZ){
                    v0 = exp2_fast(v0*ESC);
                    v1 = exp2_fast(v1*ESC);
                    rowsum += v0 + v1;
                    *reinterpret_cast<__half2*>(&Ch[(long)r*ldc + cI]) =
                        __floats2half2_rn(v0, v1);
                } else {
                    if (BIAS == 1){ v0 += bM; v1 += bM; }
                    if (BIAS == 2){ v0 += bias[cI]; v1 += bias[cI+1]; }
                    if (CHALF){
                        *reinterpret_cast<__half2*>(&Ch[(long)r*ldc + cI]) =
                            __floats2half2_rn(v0, v1);
                    } else if (SPLITK > 1){
                        atomicAdd(&Cf[(long)r*ldc + cI],     v0);
                        atomicAdd(&Cf[(long)r*ldc + cI + 1], v1);
                    } else {
                        *reinterpret_cast<float2*>(&Cf[(long)r*ldc + cI]) = make_float2(v0, v1);
                    }
                }
            }
            if (EXPZ){
                rowsum += __shfl_xor_sync(0xffffffffu, rowsum, 1);
                rowsum += __shfl_xor_sync(0xffffffffu, rowsum, 2);
                // per-(mtile, column-warp) slot: race-free plain store
                if (t4 == 0)
                    Zp[((long)(blockIdx.x*WCOLS + wx)*(BATCH*NH) + z)*HW_N + r] = rowsum;
            }
        }
    }
}

// ---------------- gating: channel-split partial dot products ----------------
__global__ void gate_part(const float* __restrict__ gw)
{
    int i = blockIdx.x*256 + threadIdx.x;    // over BATCH*HW_N
    int b = i / HW_N, m = i % HW_N;
    int c0 = blockIdx.y*32;
    const float* xb = g_x2 + (long)b*CH*HW_N + m;
    const float* yb = g_y2 + (long)b*CH*HW_N + m;
    float s0 = 0.f, s1 = 0.f;
    #pragma unroll 8
    for (int c = c0; c < c0+32; c++){
        float xv = xb[(long)c*HW_N];
        s0 = fmaf(gw[c],      xv, s0);
        s1 = fmaf(gw[C2 + c], xv, s1);
    }
    #pragma unroll 8
    for (int c = c0; c < c0+32; c++){
        float yv = yb[(long)c*HW_N];
        s0 = fmaf(gw[CH + c],      yv, s0);
        s1 = fmaf(gw[C2 + CH + c], yv, s1);
    }
    atomicAdd(&g_gacc[b*2*HW_N + m],        s0);
    atomicAdd(&g_gacc[b*2*HW_N + HW_N + m], s1);
}

// ---------------- final gated writeback (sigmoid inline) ----------------
__global__ void final_kernel(float* __restrict__ out, const float* __restrict__ gb)
{
    long i = (long)blockIdx.x*blockDim.x + threadIdx.x;
    if (i >= (long)BATCH*CH*HW_N) return;
    int b = (int)(i / (CH*HW_N));
    int m = (int)(i % HW_N);
    float g0 = 1.f + sigmoidf_(g_gacc[b*2*HW_N + m]        + gb[0]);
    float g1 = 1.f + sigmoidf_(g_gacc[b*2*HW_N + HW_N + m] + gb[1]);
    out[i]                       = g_x2[i] * g0;
    out[(long)BATCH*CH*HW_N + i] = g_y2[i] * g1;
}

// ---------------- host orchestration ----------------
extern "C" void kernel_launch(void* const* d_in, const int* in_sizes, int n_in,
                              void* d_out, int out_size)
{
    const float* x      = (const float*)d_in[0];
    const float* y      = (const float*)d_in[1];
    const float* fc1w   = (const float*)d_in[2];
    const float* fc1b   = (const float*)d_in[3];
    const float* fc2w   = (const float*)d_in[4];
    const float* fc2b   = (const float*)d_in[5];
    const float* t1_qw  = (const float*)d_in[6];
    const float* t1_qb  = (const float*)d_in[7];
    const float* t1_kw  = (const float*)d_in[8];
    const float* t1_kb  = (const float*)d_in[9];
    const float* t1_vw  = (const float*)d_in[10];
    const float* t1_vb  = (const float*)d_in[11];
    const float* t2_qw  = (const float*)d_in[12];
    const float* t2_qb  = (const float*)d_in[13];
    const float* t2_kw  = (const float*)d_in[14];
    const float* t2_kb  = (const float*)d_in[15];
    const float* t2_vw  = (const float*)d_in[16];
    const float* t2_vb  = (const float*)d_in[17];
    const float* gate_w = (const float*)d_in[18];
    const float* gate_b = (const float*)d_in[19];

    float *x2, *y2, *Zpart, *kvb1, *kvb2;
    __half *xs, *ys, *q, *kv, *S, *x2h, *wt1h, *wt2h, *wkv1, *wkv2;
    cudaGetSymbolAddress((void**)&xs,    g_xs);
    cudaGetSymbolAddress((void**)&ys,    g_ys);
    cudaGetSymbolAddress((void**)&q,     g_q);
    cudaGetSymbolAddress((void**)&kv,    g_kv);
    cudaGetSymbolAddress((void**)&S,     g_S);
    cudaGetSymbolAddress((void**)&x2,    g_x2);
    cudaGetSymbolAddress((void**)&y2,    g_y2);
    cudaGetSymbolAddress((void**)&x2h,   g_x2h);
    cudaGetSymbolAddress((void**)&Zpart, g_Zpart);
    cudaGetSymbolAddress((void**)&wt1h,  g_wt1h);
    cudaGetSymbolAddress((void**)&wt2h,  g_wt2h);
    cudaGetSymbolAddress((void**)&wkv1,  g_wkv1);
    cudaGetSymbolAddress((void**)&wkv2,  g_wkv2);
    cudaGetSymbolAddress((void**)&kvb1,  g_kvb1);
    cudaGetSymbolAddress((void**)&kvb2,  g_kvb2);

    const long total = (long)BATCH*CH*HW_N;
    const long long NN  = (long long)HW_N*HW_N;
    const long long CN  = (long long)CH*HW_N;
    const long long HN  = (long long)DK*HW_N;

    // --- prologue (slot 4 = first q-conv GEMM for ncu) ---
    prep_kernel<<<128 + 1024 + 1 + BATCH*C2, 256>>>(x, y,
        t1_qw, t2_qw, t1_kw, t1_vw, t1_kb, t1_vb,
        t2_kw, t2_vw, t2_kb, t2_vb);                                    // 1
    se_kernel<<<BATCH, C2>>>(fc1w, fc1b, fc2w, fc2b);                   // 2
    scale_kernel<<<(int)((total + 255)/256), 256>>>(x, y);              // 3

    auto rtrans = [&](const __half* qin, const __half* kvin,
                      const __half* wtq, const float* qb,
                      const __half* wkv, const float* kvb, float* outp)
    {
        // q_t[b][n][c] = sum_c' qin[b][c'][n] * wtq[c'][c] + qb[c]
        hgemm<32,3, 128,64,32,32, true,2,false,true,1>
            <<<dim3(CH/64, HW_N/128, BATCH), 256>>>(
            qin, wtq, q, qb, nullptr,
            CH, HW_N, CH, CH,
            1, CN, 0, 0, 0, CN, 0);
        // kv[b][o][n] = sum_c wkv[o][c]*kvin[b][c][n] + kvb[o]
        hgemm<32,3, 128,128,64,32, false,1,false,true,1>
            <<<dim3(HW_N/128, C2/128, BATCH), 256>>>(
            wkv, kvin, kv, kvb, nullptr,
            CH, CH, HW_N, HW_N,
            1, 0, 0, CN, 0, (long long)C2*HW_N, 0);
        // E[z][n][m] = half(exp2(S*ESC)); Zpart[(mtile,wx)][z][n] = warp row sums
        hgemm<64,1, 128,128,64,32, false,0,true,false,1>
            <<<dim3(HW_N/128, HW_N/128, BATCH*NH), 256>>>(
            q, kv, S, nullptr, Zpart,
            DK, CH, HW_N, HW_N,
            NH, (long long)HW_N*CH, DK, (long long)C2*HW_N, HN,
            (long long)NH*NN, NN);
        zinv_kernel<<<(BATCH*NH*HW_N + 255)/256, 256>>>();
        vscale_kernel<<<(int)((total + 255)/256), 256>>>();
        zfill_kernel<<<(int)((total + 255)/256), 256>>>(outp, (int)total);
        // out[b][h*64+d][m] = sum_n vZ[d][n] * E[z][n][m]   (split-K=3)
        hgemm<32,3, 64,128,32,32, false,0,false,false,3>
            <<<dim3(HW_N/128, 3, BATCH*NH), 256>>>(
            kv + (long)CH*HW_N, S, outp, nullptr, nullptr,
            HW_N, HW_N, HW_N, HW_N,
            NH, (long long)C2*HW_N, HN, (long long)NH*NN, NN, CN, HN);
    };

    // RTrans 1: x = attn(q=xs, k=ys, v=ys)
    rtrans(xs, ys, wt1h, t1_qb, wkv1, kvb1, x2);
    f2h_kernel<<<(int)((total + 255)/256), 256>>>(x2, x2h, (int)total);
    // RTrans 2: y = attn(q=ys, k=x2, v=x2)
    rtrans(ys, x2h, wt2h, t2_qb, wkv2, kvb2, y2);

    // --- RGating + final writeback ---
    gate_part<<<dim3((BATCH*HW_N)/256, CH/32), 256>>>(gate_w);
    final_kernel<<<(int)((total + 255)/256), 256>>>((float*)d_out, gate_b);
}

// round 10
// speedup vs baseline: 2.6309x; 1.0165x over previous
#include <cuda_runtime.h>
#include <cuda_fp16.h>
#include <math.h>
#include <stdint.h>

// ---------------- problem constants ----------------
#define BATCH 2
#define CH    256
#define NH    4
#define DK    64          // CH / NH
#define HW_N  2304        // 48*48
#define C2    512         // 2*CH
#define C3    768         // 3*CH (q,k,v packed)
#define MTILES 18         // HW_N / 128
#define ZPARTS (MTILES*4) // per-(mtile, column-warp) partials

#define ESC 0.18033688011112042f   // 0.125 * log2(e)

// ---------------- scratch (device globals) ----------
__device__ __half g_xs[BATCH*CH*HW_N];
__device__ __half g_ys[BATCH*CH*HW_N];
__device__ __half g_qkv[BATCH*C3*HW_N];           // rows 0-255 q, 256-511 k, 512-767 v  [b][c][n]
__device__ float  g_x2[BATCH*CH*HW_N];
__device__ float  g_y2[BATCH*CH*HW_N];
__device__ __half g_x2h[BATCH*CH*HW_N];
__device__ float  g_part[3*BATCH*CH*HW_N];        // split-K partials
__device__ __half g_S [(size_t)BATCH*NH*HW_N*HW_N]; // 85 MB: E = exp(S*0.125)
__device__ float  g_Z [BATCH*NH*HW_N];            // invZ
__device__ float  g_Zpart[ZPARTS*BATCH*NH*HW_N];  // per-(mtile,wx) partial row sums
__device__ __half g_wqkv1[C3*CH];
__device__ __half g_wqkv2[C3*CH];
__device__ float  g_qkvb1[C3];
__device__ float  g_qkvb2[C3];
__device__ float  g_pooled[BATCH*C2];
__device__ float  g_sescale[BATCH*C2];            // 1 + sigmoid(f)
__device__ float  g_gacc[BATCH*2*HW_N];           // gate pre-sigmoid accumulators

__device__ __forceinline__ float sigmoidf_(float v){ return 1.f/(1.f+expf(-v)); }

__device__ __forceinline__ float exp2_fast(float x)
{
    x = fminf(fmaxf(x, -60.f), 60.f);
    float m  = x + 12582912.0f;
    float rn = m - 12582912.0f;
    float r  = x - rn;
    int   iv = __float_as_int(m) - 0x4B400000;
    float p  = 0.0096181291f;
    p = fmaf(p, r, 0.0555041086f);
    p = fmaf(p, r, 0.2402265069f);
    p = fmaf(p, r, 0.6931471806f);
    p = fmaf(p, r, 1.0f);
    return p * __int_as_float((iv + 127) << 23);
}

__device__ __forceinline__ uint32_t smaddr(const void* p){
    return (uint32_t)__cvta_generic_to_shared(p);
}
__device__ __forceinline__ void cpa16(uint32_t dst, const void* src){
    asm volatile("cp.async.cg.shared.global [%0], [%1], 16;" :: "r"(dst), "l"(src));
}
__device__ __forceinline__ void cpa_commit(){
    asm volatile("cp.async.commit_group;" ::: "memory");
}
__device__ __forceinline__ void ldm_x4(uint32_t &r0, uint32_t &r1, uint32_t &r2, uint32_t &r3,
                                       uint32_t a){
    asm volatile("ldmatrix.sync.aligned.m8n8.x4.shared.b16 {%0,%1,%2,%3}, [%4];"
        : "=r"(r0),"=r"(r1),"=r"(r2),"=r"(r3) : "r"(a));
}
__device__ __forceinline__ void ldm_x4t(uint32_t &r0, uint32_t &r1, uint32_t &r2, uint32_t &r3,
                                        uint32_t a){
    asm volatile("ldmatrix.sync.aligned.m8n8.x4.trans.shared.b16 {%0,%1,%2,%3}, [%4];"
        : "=r"(r0),"=r"(r1),"=r"(r2),"=r"(r3) : "r"(a));
}
__device__ __forceinline__ void mma_f16(float (&c)[4], uint32_t a0, uint32_t a1,
                                        uint32_t a2, uint32_t a3,
                                        uint32_t b0, uint32_t b1)
{
    asm volatile("mma.sync.aligned.m16n8k16.row.col.f32.f16.f16.f32 "
        "{%0,%1,%2,%3}, {%4,%5,%6,%7}, {%8,%9}, {%0,%1,%2,%3};"
        : "+f"(c[0]), "+f"(c[1]), "+f"(c[2]), "+f"(c[3])
        : "r"(a0), "r"(a1), "r"(a2), "r"(a3), "r"(b0), "r"(b1));
}

// ---- prep: qkv weight/bias pack (both rtrans) + gacc zero + channel pooling ----
__global__ void prep_kernel(const float* __restrict__ x, const float* __restrict__ y,
                            const float* __restrict__ qw1, const float* __restrict__ kw1,
                            const float* __restrict__ vw1,
                            const float* __restrict__ qb1, const float* __restrict__ kb1,
                            const float* __restrict__ vb1,
                            const float* __restrict__ qw2, const float* __restrict__ kw2,
                            const float* __restrict__ vw2,
                            const float* __restrict__ qb2, const float* __restrict__ kb2,
                            const float* __restrict__ vb2)
{
    int bid = blockIdx.x, t = threadIdx.x;
    if (bid < 1536){                                 // qkv weight pack: 2*768*256 elems
        int idx = bid*256 + t;
        int which = idx / (C3*CH);
        int li = idx % (C3*CH);
        int row = li / CH, col = li % CH;
        const float* w;
        int lr;
        if (row < CH)      { w = which ? qw2 : qw1; lr = row; }
        else if (row < C2) { w = which ? kw2 : kw1; lr = row - CH; }
        else               { w = which ? vw2 : vw1; lr = row - C2; }
        __half* dst = which ? g_wqkv2 : g_wqkv1;
        dst[li] = __float2half_rn(w[lr*CH + col]);
        if (li < C3){
            const float* bsrc;
            int br;
            if (li < CH)      { bsrc = which ? qb2 : qb1; br = li; }
            else if (li < C2) { bsrc = which ? kb2 : kb1; br = li - CH; }
            else              { bsrc = which ? vb2 : vb1; br = li - C2; }
            float* db = which ? g_qkvb2 : g_qkvb1;
            db[li] = bsrc[br];
        }
    } else if (bid == 1536){                         // zero gate accumulators
        for (int j = t; j < BATCH*2*HW_N; j += 256) g_gacc[j] = 0.f;
    } else {                                         // channel-mean pooling
        int idx = bid - 1537;                        // over BATCH*C2
        int b = idx / C2, ch = idx % C2;
        const float* src = (ch < CH) ? (x + ((long)b*CH + ch)*HW_N)
                                     : (y + ((long)b*CH + (ch-CH))*HW_N);
        float s = 0.f;
        for (int i = t; i < HW_N; i += 256) s += src[i];
        __shared__ float red[256];
        red[t] = s; __syncthreads();
        for (int st = 128; st > 0; st >>= 1){
            if (t < st) red[t] += red[t+st];
            __syncthreads();
        }
        if (t == 0) g_pooled[idx] = red[0] / (float)HW_N;
    }
}

// ---------------- SE MLP (tiny, 2 blocks) ----------------
__global__ void se_kernel(const float* __restrict__ w1, const float* __restrict__ b1,
                          const float* __restrict__ w2, const float* __restrict__ b2)
{
    int b = blockIdx.x, t = threadIdx.x;   // 512 threads
    __shared__ float sp[C2], sh[DK];
    sp[t] = g_pooled[b*C2 + t];
    __syncthreads();
    if (t < DK) {
        float s = b1[t];
        for (int c = 0; c < C2; c++) s += w1[t*C2 + c] * sp[c];
        sh[t] = fmaxf(s, 0.f);
    }
    __syncthreads();
    float f = b2[t];
    for (int j = 0; j < DK; j++) f += w2[t*DK + j] * sh[j];
    g_sescale[b*C2 + t] = 1.f + sigmoidf_(f);
}

// ---------------- elementwise SE scale (coalesced) ----------------
__global__ void scale_kernel(const float* __restrict__ x, const float* __restrict__ y)
{
    long i = (long)blockIdx.x*blockDim.x + threadIdx.x;
    if (i >= (long)BATCH*CH*HW_N) return;
    int b = (int)(i / (CH*HW_N));
    int c = (int)((i / HW_N) % CH);
    g_xs[i] = __float2half_rn(x[i] * g_sescale[b*C2 + c]);
    g_ys[i] = __float2half_rn(y[i] * g_sescale[b*C2 + CH + c]);
}

// invZ from ZPARTS partials
__global__ void zinv_kernel()
{
    int i = blockIdx.x*blockDim.x + threadIdx.x;
    if (i >= BATCH*NH*HW_N) return;
    float s = 0.f;
    #pragma unroll
    for (int p = 0; p < ZPARTS; p++) s += g_Zpart[(long)p*(BATCH*NH*HW_N) + i];
    g_Z[i] = 1.0f / s;
}

// scale v rows (g_qkv rows 512..767) by invZ[(b,h,n)]
__global__ void vscale_kernel()
{
    long i = (long)blockIdx.x*blockDim.x + threadIdx.x;
    if (i >= (long)BATCH*CH*HW_N) return;
    int b = (int)(i / (CH*HW_N));
    int c = (int)((i / HW_N) % CH);
    int n = (int)(i % HW_N);
    long off = ((long)b*C3 + C2 + c)*HW_N + n;
    float z = g_Z[((long)b*NH + (c >> 6))*HW_N + n];
    g_qkv[off] = __float2half_rn(__half2float(g_qkv[off]) * z);
}

// sum 3 split-K partials -> float dst (+ optional half shadow)
__global__ void psum_kernel(float* __restrict__ dst, __half* __restrict__ dsth)
{
    long i = (long)blockIdx.x*blockDim.x + threadIdx.x;
    const long total = (long)BATCH*CH*HW_N;
    if (i >= total) return;
    float s = g_part[i] + g_part[total + i] + g_part[2*total + i];
    dst[i] = s;
    if (dsth) dsth[i] = __float2half_rn(s);
}

// ================= all-half cp.async tensor-core GEMM =================
// QSEL: B operand = (blockIdx.y < 2) ? Bq : B  (merged qkv conv: rows<256 use q-input)
template<int BK, int ST, int BM, int BN, int WM, int WN,
         bool TRA, int BIAS, bool EXPZ, bool CHALF, int SPLITK, bool QSEL>
__global__ void __launch_bounds__(256)
hgemm(const __half* __restrict__ A, const __half* __restrict__ B,
      const __half* __restrict__ Bq,
      void* __restrict__ Cv, const float* __restrict__ bias,
      float* __restrict__ Zp,
      int K, int lda, int ldb, int ldc, int zdiv,
      long long sA1, long long sA2, long long sB1, long long sB2,
      long long sC1, long long sC2, long long sSplit)
{
    constexpr int WCOLS = BN / WN;
    constexpr int MF = WM / 16;
    constexpr int NF = WN / 8;
    constexpr int PAD = 8;
    constexpr int A_CH = (BM*BK/8)/256;
    constexpr int B_CH = (BK*BN/8)/256;

    __shared__ __half As[ST][TRA ? BK : BM][(TRA ? BM : BK) + PAD];
    __shared__ __half Bs[ST][BK][BN + PAD];

    int z  = blockIdx.z;
    int z1 = z / zdiv, z2 = z - z1*zdiv;
    A += z1*sA1 + z2*sA2;
    if (QSEL && blockIdx.y < 2) B = Bq;
    B += z1*sB1 + z2*sB2;
    float*  Cf = (EXPZ || CHALF) ? nullptr : ((float*)Cv + z1*sC1 + z2*sC2);
    __half* Ch = (EXPZ || CHALF) ? ((__half*)Cv + z1*sC1 + z2*sC2) : nullptr;
    if (SPLITK > 1) Cf += (long)blockIdx.y * sSplit;

    int bm, kbase, Keff;
    if (SPLITK > 1){ bm = 0; kbase = blockIdx.y*(K/SPLITK); Keff = K/SPLITK; }
    else           { bm = blockIdx.y*BM; kbase = 0; Keff = K; }
    int bn = blockIdx.x*BN;

    int t    = threadIdx.x;
    int warp = t >> 5, lane = t & 31;
    int g = lane >> 2, t4 = lane & 3;
    int wy = warp / WCOLS, wx = warp % WCOLS;

    auto issue = [&](int s, int k0){
        #pragma unroll
        for (int i = 0; i < A_CH; i++){
            int idx = t + 256*i;
            if (TRA){
                int k = idx/(BM/8), m8 = idx%(BM/8);
                cpa16(smaddr(&As[s][k][m8*8]), &A[(long)(k0+k)*lda + bm + m8*8]);
            } else {
                int m = idx/(BK/8), k8 = idx%(BK/8);
                cpa16(smaddr(&As[s][m][k8*8]), &A[(long)(bm+m)*lda + k0 + k8*8]);
            }
        }
        #pragma unroll
        for (int i = 0; i < B_CH; i++){
            int idx = t + 256*i;
            int k = idx/(BN/8), n8 = idx%(BN/8);
            cpa16(smaddr(&Bs[s][k][n8*8]), &B[(long)(k0+k)*ldb + bn + n8*8]);
        }
        cpa_commit();
    };

    float acc[MF][NF][4] = {};

    int nT = Keff / BK;
    issue(0, kbase);
    if (ST > 1 && nT > 1) issue(1, kbase + BK);

    for (int tI = 0; tI < nT; tI++){
        if (ST > 1 && tI < nT-1) asm volatile("cp.async.wait_group 1;" ::: "memory");
        else                     asm volatile("cp.async.wait_group 0;" ::: "memory");
        __syncthreads();
        if (ST > 1 && tI + 2 < nT) issue((tI+2)%ST, kbase + (tI+2)*BK);

        int cur = tI % ST;
        #pragma unroll
        for (int kc = 0; kc < BK/16; kc++){
            uint32_t af[MF][4]; uint32_t bf[NF][2];
            #pragma unroll
            for (int mf = 0; mf < MF; mf++){
                if (TRA){
                    uint32_t r0,r1,r2,r3;
                    uint32_t a = smaddr(&As[cur][kc*16 + (lane & 15)]
                                                [wy*WM + mf*16 + ((lane >> 4) << 3)]);
                    ldm_x4t(r0, r1, r2, r3, a);
                    af[mf][0]=r0; af[mf][1]=r2; af[mf][2]=r1; af[mf][3]=r3;
                } else {
                    uint32_t a = smaddr(&As[cur][wy*WM + mf*16 + (lane & 15)]
                                                [kc*16 + ((lane >> 4) << 3)]);
                    ldm_x4(af[mf][0], af[mf][1], af[mf][2], af[mf][3], a);
                }
            }
            #pragma unroll
            for (int nf2 = 0; nf2 < NF/2; nf2++){
                uint32_t a = smaddr(&Bs[cur][kc*16 + (lane & 15)]
                                            [wx*WN + nf2*16 + ((lane >> 4) << 3)]);
                ldm_x4t(bf[nf2*2][0], bf[nf2*2][1], bf[nf2*2+1][0], bf[nf2*2+1][1], a);
            }
            #pragma unroll
            for (int mf = 0; mf < MF; mf++)
                #pragma unroll
                for (int nf = 0; nf < NF; nf++)
                    mma_f16(acc[mf][nf], af[mf][0], af[mf][1], af[mf][2], af[mf][3],
                            bf[nf][0], bf[nf][1]);
        }
    }

    // ---------------- epilogue ----------------
    #pragma unroll
    for (int mf = 0; mf < MF; mf++){
        int rbase = bm + wy*WM + mf*16 + g;
        #pragma unroll
        for (int half = 0; half < 2; half++){
            int r = rbase + half*8;
            float bM = (BIAS == 1) ? bias[r] : 0.f;
            float rowsum = 0.f;
            #pragma unroll
            for (int nf = 0; nf < NF; nf++){
                int cI = bn + wx*WN + nf*8 + t4*2;
                float v0 = acc[mf][nf][half*2 + 0];
                float v1 = acc[mf][nf][half*2 + 1];
                if (EXPZ){
                    v0 = exp2_fast(v0*ESC);
                    v1 = exp2_fast(v1*ESC);
                    rowsum += v0 + v1;
                    *reinterpret_cast<__half2*>(&Ch[(long)r*ldc + cI]) =
                        __floats2half2_rn(v0, v1);
                } else {
                    if (BIAS == 1){ v0 += bM; v1 += bM; }
                    if (CHALF){
                        *reinterpret_cast<__half2*>(&Ch[(long)r*ldc + cI]) =
                            __floats2half2_rn(v0, v1);
                    } else {
                        *reinterpret_cast<float2*>(&Cf[(long)r*ldc + cI]) = make_float2(v0, v1);
                    }
                }
            }
            if (EXPZ){
                rowsum += __shfl_xor_sync(0xffffffffu, rowsum, 1);
                rowsum += __shfl_xor_sync(0xffffffffu, rowsum, 2);
                if (t4 == 0)
                    Zp[((long)(blockIdx.x*WCOLS + wx)*(BATCH*NH) + z)*HW_N + r] = rowsum;
            }
        }
    }
}

// ---------------- gating: channel-split partial dot products ----------------
__global__ void gate_part(const float* __restrict__ gw)
{
    int i = blockIdx.x*256 + threadIdx.x;    // over BATCH*HW_N
    int b = i / HW_N, m = i % HW_N;
    int c0 = blockIdx.y*32;
    const float* xb = g_x2 + (long)b*CH*HW_N + m;
    const float* yb = g_y2 + (long)b*CH*HW_N + m;
    float s0 = 0.f, s1 = 0.f;
    #pragma unroll 8
    for (int c = c0; c < c0+32; c++){
        float xv = xb[(long)c*HW_N];
        s0 = fmaf(gw[c],      xv, s0);
        s1 = fmaf(gw[C2 + c], xv, s1);
    }
    #pragma unroll 8
    for (int c = c0; c < c0+32; c++){
        float yv = yb[(long)c*HW_N];
        s0 = fmaf(gw[CH + c],      yv, s0);
        s1 = fmaf(gw[C2 + CH + c], yv, s1);
    }
    atomicAdd(&g_gacc[b*2*HW_N + m],        s0);
    atomicAdd(&g_gacc[b*2*HW_N + HW_N + m], s1);
}

// ---------------- final gated writeback (sigmoid inline) ----------------
__global__ void final_kernel(float* __restrict__ out, const float* __restrict__ gb)
{
    long i = (long)blockIdx.x*blockDim.x + threadIdx.x;
    if (i >= (long)BATCH*CH*HW_N) return;
    int b = (int)(i / (CH*HW_N));
    int m = (int)(i % HW_N);
    float g0 = 1.f + sigmoidf_(g_gacc[b*2*HW_N + m]        + gb[0]);
    float g1 = 1.f + sigmoidf_(g_gacc[b*2*HW_N + HW_N + m] + gb[1]);
    out[i]                       = g_x2[i] * g0;
    out[(long)BATCH*CH*HW_N + i] = g_y2[i] * g1;
}

// ---------------- host orchestration ----------------
extern "C" void kernel_launch(void* const* d_in, const int* in_sizes, int n_in,
                              void* d_out, int out_size)
{
    const float* x      = (const float*)d_in[0];
    const float* y      = (const float*)d_in[1];
    const float* fc1w   = (const float*)d_in[2];
    const float* fc1b   = (const float*)d_in[3];
    const float* fc2w   = (const float*)d_in[4];
    const float* fc2b   = (const float*)d_in[5];
    const float* t1_qw  = (const float*)d_in[6];
    const float* t1_qb  = (const float*)d_in[7];
    const float* t1_kw  = (const float*)d_in[8];
    const float* t1_kb  = (const float*)d_in[9];
    const float* t1_vw  = (const float*)d_in[10];
    const float* t1_vb  = (const float*)d_in[11];
    const float* t2_qw  = (const float*)d_in[12];
    const float* t2_qb  = (const float*)d_in[13];
    const float* t2_kw  = (const float*)d_in[14];
    const float* t2_kb  = (const float*)d_in[15];
    const float* t2_vw  = (const float*)d_in[16];
    const float* t2_vb  = (const float*)d_in[17];
    const float* gate_w = (const float*)d_in[18];
    const float* gate_b = (const float*)d_in[19];

    float *x2, *y2, *qkvb1, *qkvb2;
    __half *xs, *ys, *qkv, *S, *x2h, *wqkv1, *wqkv2;
    cudaGetSymbolAddress((void**)&xs,    g_xs);
    cudaGetSymbolAddress((void**)&ys,    g_ys);
    cudaGetSymbolAddress((void**)&qkv,   g_qkv);
    cudaGetSymbolAddress((void**)&S,     g_S);
    cudaGetSymbolAddress((void**)&x2,    g_x2);
    cudaGetSymbolAddress((void**)&y2,    g_y2);
    cudaGetSymbolAddress((void**)&x2h,   g_x2h);
    cudaGetSymbolAddress((void**)&wqkv1, g_wqkv1);
    cudaGetSymbolAddress((void**)&wqkv2, g_wqkv2);
    cudaGetSymbolAddress((void**)&qkvb1, g_qkvb1);
    cudaGetSymbolAddress((void**)&qkvb2, g_qkvb2);

    float* Zpart;
    cudaGetSymbolAddress((void**)&Zpart, g_Zpart);
    float* part;
    cudaGetSymbolAddress((void**)&part, g_part);

    const long total = (long)BATCH*CH*HW_N;
    const long long NN   = (long long)HW_N*HW_N;
    const long long CN   = (long long)CH*HW_N;
    const long long HN   = (long long)DK*HW_N;
    const long long C3N  = (long long)C3*HW_N;

    // --- prologue (slot 4 = merged qkv-conv for ncu) ---
    prep_kernel<<<1537 + BATCH*C2, 256>>>(x, y,
        t1_qw, t1_kw, t1_vw, t1_qb, t1_kb, t1_vb,
        t2_qw, t2_kw, t2_vw, t2_qb, t2_kb, t2_vb);                      // 1
    se_kernel<<<BATCH, C2>>>(fc1w, fc1b, fc2w, fc2b);                   // 2
    scale_kernel<<<(int)((total + 255)/256), 256>>>(x, y);              // 3

    auto rtrans = [&](const __half* qin, const __half* kvin,
                      const __half* wqkv, const float* qkvb,
                      float* outp, __half* outph)
    {
        // merged conv: qkv[b][o][n] = sum_c w[o][c]*in_sel[b][c][n] + b[o]
        //   rows 0-255 (blockIdx.y<2) read qin; rows 256-767 read kvin
        hgemm<32,3, 128,128,64,32, false,1,false,true,1,true>
            <<<dim3(HW_N/128, C3/128, BATCH), 256>>>(
            wqkv, kvin, qin, qkv, qkvb, nullptr,
            CH, CH, HW_N, HW_N,
            1, 0, 0, CN, 0, C3N, 0, 0);
        // scores: E[z][n][m] = half(exp2(S*ESC)); Zpart row sums
        //   A = q rows (TRA: q stored [c][n]), B = k rows
        hgemm<64,1, 128,128,64,32, true,0,true,false,1,false>
            <<<dim3(HW_N/128, HW_N/128, BATCH*NH), 256>>>(
            qkv, qkv + (long)CH*HW_N, nullptr, S, nullptr, Zpart,
            DK, HW_N, HW_N, HW_N,
            NH, C3N, HN, C3N, HN,
            (long long)NH*NN, NN, 0);
        zinv_kernel<<<(BATCH*NH*HW_N + 255)/256, 256>>>();
        vscale_kernel<<<(int)((total + 255)/256), 256>>>();
        // PV split-K=3 into disjoint partial buffers (plain stores)
        hgemm<32,3, 64,128,32,32, false,0,false,false,3,false>
            <<<dim3(HW_N/128, 3, BATCH*NH), 256>>>(
            qkv + (long)C2*HW_N, S, nullptr, part, nullptr, nullptr,
            HW_N, HW_N, HW_N, HW_N,
            NH, C3N, HN, (long long)NH*NN, NN, CN, HN, total);
        // partial sum -> float out (+ half shadow)
        psum_kernel<<<(int)((total + 255)/256), 256>>>(outp, outph);
    };

    // RTrans 1: x = attn(q=xs, k=ys, v=ys)
    rtrans(xs, ys, wqkv1, qkvb1, x2, x2h);
    // RTrans 2: y = attn(q=ys, k=x2, v=x2)
    rtrans(ys, x2h, wqkv2, qkvb2, y2, nullptr);

    // --- RGating + final writeback ---
    gate_part<<<dim3((BATCH*HW_N)/256, CH/32), 256>>>(gate_w);
    final_kernel<<<(int)((total + 255)/256), 256>>>((float*)d_out, gate_b);
}